// round 7
// baseline (speedup 1.0000x reference)
#include <cuda_runtime.h>
#include <math.h>

// ---------------------------------------------------------------------------
// NeuralODE on GB300 (round 7): one row per CTA -> minimal sync pipeline.
//  * 1024 CTAs x 256 threads, 1 row/CTA, 3 CTAs/SM (launch_bounds 256,3)
//  * per-row exact step skipping (CTA tend = its row's tend)
//  * longest-first launch order -> LPT under HW work-stealing (~3.5 waves)
//  * layer-2: thread = (unit, k-half); W2 64 floats in regs as 32 u64,
//    16 LDS.128 + 32 fma2 + ONE shfl-xor16 reduce
//  * 3 light barriers/eval over 8 warps (vs 8-16 warps with 2-4 rows before)
//  * fma.rn.f32x2 / add.rn.f32x2, MUFU tanh.approx, __cosf
// ---------------------------------------------------------------------------

#define Bsz   1024
#define Tn    128
#define Dn    256
#define NACT  9
#define LATD  32
#define INW   43
#define NCTA  1024
#define NTH   256
#define W3P   132    // padded W3 row stride (floats) - kills i3-bank conflicts

typedef unsigned long long u64;

__device__ int g_perm[Bsz];

__device__ __forceinline__ u64 fma2(u64 a, u64 b, u64 c) {
    u64 d;
    asm("fma.rn.f32x2 %0, %1, %2, %3;" : "=l"(d) : "l"(a), "l"(b), "l"(c));
    return d;
}
__device__ __forceinline__ u64 add2(u64 a, u64 b) {
    u64 d;
    asm("add.rn.f32x2 %0, %1, %2;" : "=l"(d) : "l"(a), "l"(b));
    return d;
}
__device__ __forceinline__ float2 unpk(u64 v) {
    float2 f;
    asm("mov.b64 {%0, %1}, %2;" : "=f"(f.x), "=f"(f.y) : "l"(v));
    return f;
}
__device__ __forceinline__ float tanh_fast(float x) {
    float r;
    asm("tanh.approx.f32 %0, %1;" : "=f"(r) : "f"(x));
    return r;
}

// ---- counting sort of rows by length (stable, deterministic) --------------
__global__ void sort_kernel(const int* __restrict__ length)
{
    __shared__ int len_s[Bsz];
    __shared__ int hist[Tn];
    __shared__ int pref[Tn];
    const int tid = threadIdx.x;          // 128 threads
    for (int i = tid; i < Bsz; i += 128) {
        int v = length[i];
        len_s[i] = min(max(v, 0), Tn - 1);
    }
    if (tid < Tn) hist[tid] = 0;
    __syncthreads();
    for (int i = tid; i < Bsz; i += 128) atomicAdd(&hist[len_s[i]], 1);
    __syncthreads();
    if (tid == 0) {
        int acc = 0;
        for (int v = 0; v < Tn; v++) { pref[v] = acc; acc += hist[v]; }
    }
    __syncthreads();
    int pos = pref[tid];                  // thread tid handles bin value tid
    for (int b = 0; b < Bsz; b++)
        if (len_s[b] == tid) g_perm[pos++] = b;
}

struct __align__(16) Smem {
    float W1s[128][12];     // [unit][w1a0..8, w1t, w1c, pad]
    float W3s[NACT * W3P];
    float h1[128];
    float h2[128];
    float base1[128];       // b1 + W1[:,9:41] @ latent
    float csr[Dn];
    float Yts[12];
    float Ycur[12];
    float ksum[12];
    float b3s[16];
    float tsm[Tn];
    float tend;
    int   brow;
};

__global__ __launch_bounds__(NTH, 3)
void node_kernel(const float* __restrict__ ts, const float* __restrict__ y0,
                 const float* __restrict__ latent, const int* __restrict__ length,
                 const float* __restrict__ dense_ts, const float* __restrict__ dense_cs,
                 const float* __restrict__ W1, const float* __restrict__ b1,
                 const float* __restrict__ W2, const float* __restrict__ b2,
                 const float* __restrict__ W3, const float* __restrict__ b3,
                 float* __restrict__ out)
{
    __shared__ Smem s;
    const int tid = threadIdx.x;
    // longest-first launch: bid 0 = longest row -> LPT under work-stealing
    const int grp = (NCTA - 1) - blockIdx.x;

    if (tid == 0) {
        int b = g_perm[grp];
        s.brow = b;
        int li = max(length[b] - 1, 0);
        s.tend = ts[li];
    }
    __syncthreads();
    const int row = s.brow;

    // layer-2 mapping: warp w, lane l -> (unit u2, k-half h)
    const int w  = tid >> 5;
    const int l  = tid & 31;
    const int u2 = w * 16 + (l & 15);
    const int h  = l >> 4;               // k in [h*64, h*64+64)

    // W2 slice: 64 floats as 32 packed f32x2 (64 regs)
    u64 W2r[32];
    {
        const u64* wg = reinterpret_cast<const u64*>(W2 + u2 * 128 + h * 64);
        #pragma unroll
        for (int m = 0; m < 32; m++) W2r[m] = wg[m];
    }
    const float b2u = b2[u2];

    // ---- shared setup -----------------------------------------------------
    if (tid < 128) {
        const float* W1r = W1 + tid * INW;
        #pragma unroll
        for (int i = 0; i < NACT; i++) s.W1s[tid][i] = W1r[i];
        s.W1s[tid][9]  = W1r[41];
        s.W1s[tid][10] = W1r[42];
        s.W1s[tid][11] = 0.f;
        const float* lv = latent + row * LATD;
        float acc = b1[tid];
        #pragma unroll
        for (int li = 0; li < LATD; li++) acc = fmaf(W1r[9 + li], lv[li], acc);
        s.base1[tid] = acc;
        s.tsm[tid] = ts[tid];
    }
    for (int idx = tid; idx < NACT * 128; idx += NTH)
        s.W3s[(idx >> 7) * W3P + (idx & 127)] = W3[idx];
    if (tid < NACT) s.b3s[tid] = b3[tid];
    s.csr[tid] = dense_cs[row * Dn + tid];
    if (tid < 12) { s.Yts[tid] = 0.f; s.Ycur[tid] = 0.f; s.ksum[tid] = 0.f; }
    __syncthreads();
    if (tid == 0) {
        float y = y0[row];
        s.Yts[0] = y; s.Ycur[0] = y;
        out[row * Tn] = y;               // t = 0 sample
    }
    __syncthreads();

    // ---- time integration -------------------------------------------------
    for (int step = 0; step < Tn - 1; step++) {
        const float ta  = s.tsm[step];
        const float dtf = (s.tsm[step + 1] - ta) * 0.5f;
        if (ta <= s.tend) {
            for (int sub = 0; sub < 2; sub++) {
                const float t0 = ta + sub * dtf;
                for (int st = 0; st < 4; st++) {
                    const float t = t0 + ((st == 0) ? 0.f : (st == 3) ? dtf : 0.5f * dtf);

                    // ---- layer 1 (threads 0..127, one unit each) ----
                    if (tid < 128) {
                        int ii = (int)ceilf(t);
                        ii = max(1, min(Dn - 1, ii));
                        float wc = t - (float)(ii - 1);
                        wc = fminf(fmaxf(wc, 0.f), 1.f);
                        float cl = s.csr[ii - 1];
                        float c  = fmaf(wc, s.csr[ii] - cl, cl);
                        float4 wA = *reinterpret_cast<const float4*>(&s.W1s[tid][0]);
                        float4 wB = *reinterpret_cast<const float4*>(&s.W1s[tid][4]);
                        float4 wC = *reinterpret_cast<const float4*>(&s.W1s[tid][8]);
                        float4 yA = *reinterpret_cast<const float4*>(&s.Yts[0]);
                        float4 yB = *reinterpret_cast<const float4*>(&s.Yts[4]);
                        float  y8 = s.Yts[8];
                        // two accumulator chains for ILP
                        float a0 = s.base1[tid];
                        float a1 = wC.y * t;             // w1t * t
                        a0 = fmaf(wA.x, yA.x, a0);
                        a1 = fmaf(wC.z, c,    a1);       // w1c * c
                        a0 = fmaf(wA.y, yA.y, a0);
                        a1 = fmaf(wA.z, yA.z, a1);
                        a0 = fmaf(wA.w, yA.w, a0);
                        a1 = fmaf(wB.x, yB.x, a1);
                        a0 = fmaf(wB.y, yB.y, a0);
                        a1 = fmaf(wB.z, yB.z, a1);
                        a0 = fmaf(wB.w, yB.w, a0);
                        a1 = fmaf(wC.x, y8,   a1);
                        s.h1[tid] = tanh_fast(a0 + a1);
                    }
                    __syncthreads();

                    // ---- layer 2: register W2 half, ONE shfl reduce ----
                    {
                        u64 a0 = 0ull, a1 = 0ull;
                        const ulonglong2* hb =
                            reinterpret_cast<const ulonglong2*>(s.h1 + h * 64);
                        #pragma unroll
                        for (int m = 0; m < 16; m++) {
                            ulonglong2 v = hb[m];
                            a0 = fma2(W2r[2 * m],     v.x, a0);
                            a1 = fma2(W2r[2 * m + 1], v.y, a1);
                        }
                        a0 = add2(a0, a1);
                        a0 = add2(a0, __shfl_xor_sync(0xffffffffu, a0, 16));
                        float2 f = unpk(a0);
                        if (h == 0)
                            s.h2[u2] = tanh_fast(f.x + f.y + b2u);
                    }
                    __syncthreads();

                    // ---- layer 3 + constraint + gating + RK bookkeeping ----
                    // 72 threads = warps 0,1 full + lanes 0..7 of warp 2
                    if (tid < 72) {
                        const unsigned mask = (tid < 64) ? 0xffffffffu : 0x000000ffu;
                        const int q  = tid & 7;      // 16-k slice
                        const int i3 = tid >> 3;     // output unit 0..8
                        const float4* wv = reinterpret_cast<const float4*>(&s.W3s[i3 * W3P + q * 16]);
                        const float4* hv = reinterpret_cast<const float4*>(&s.h2[q * 16]);
                        float ax = 0.f, ay = 0.f, az = 0.f, aw = 0.f;
                        #pragma unroll
                        for (int kk = 0; kk < 4; kk++) {
                            float4 a = wv[kk], b = hv[kk];
                            ax = fmaf(a.x, b.x, ax);
                            ay = fmaf(a.y, b.y, ay);
                            az = fmaf(a.z, b.z, az);
                            aw = fmaf(a.w, b.w, aw);
                        }
                        float acc = (ax + ay) + (az + aw);
                        acc += __shfl_xor_sync(mask, acc, 1);
                        acc += __shfl_xor_sync(mask, acc, 2);
                        acc += __shfl_xor_sync(mask, acc, 4);
                        if (q == 0) {
                            acc += s.b3s[i3];
                            if (i3 == 0) acc = -__cosf(acc);
                            if (t > s.tend) acc = 0.f;       // per-sample stop
                            float ks;
                            if (st == 0) { ks = acc; s.ksum[i3] = ks; }
                            else {
                                ks = s.ksum[i3];
                                if (st < 3) { ks += 2.f * acc; s.ksum[i3] = ks; }
                            }
                            if (st < 3) {
                                float cY = (st == 2) ? dtf : 0.5f * dtf;
                                s.Yts[i3] = s.Ycur[i3] + cY * acc;
                            } else {
                                float y = s.Ycur[i3]
                                        + (dtf * (1.0f / 6.0f)) * (ks + acc);
                                s.Ycur[i3] = y;
                                s.Yts[i3]  = y;
                            }
                        }
                    }
                    __syncthreads();
                }
            }
        }
        if (tid == 0)
            out[row * Tn + step + 1] = s.Ycur[0];
    }
}

extern "C" void kernel_launch(void* const* d_in, const int* in_sizes, int n_in,
                              void* d_out, int out_size)
{
    (void)in_sizes; (void)n_in; (void)out_size;
    sort_kernel<<<1, 128>>>((const int*)d_in[3]);
    node_kernel<<<NCTA, NTH>>>(
        (const float*)d_in[0],   // ts
        (const float*)d_in[1],   // y0
        (const float*)d_in[2],   // latent_vec
        (const int*)  d_in[3],   // length
        (const float*)d_in[4],   // dense_ts (arange -> index math)
        (const float*)d_in[5],   // dense_cs
        (const float*)d_in[6],   // W1
        (const float*)d_in[7],   // b1
        (const float*)d_in[8],   // W2
        (const float*)d_in[9],   // b2
        (const float*)d_in[10],  // W3
        (const float*)d_in[11],  // b3
        (float*)d_out);
}

// round 9
// speedup vs baseline: 1.1503x; 1.1503x over previous
#include <cuda_runtime.h>
#include <math.h>

// ---------------------------------------------------------------------------
// NeuralODE on GB300 (round 9 = round 8 resubmit; prior bench was an infra
// failure, theory untested).
//
// Diagnosis r2-r7: every layer-2 variant streamed private h1/W2 k-slices
// through the smem crossbar (~512 wavefronts/row-eval) -> L1 pipe 70-83% was
// THE roofline; instruction-count tricks never moved it. Fix here: k-half is
// per-WARP, so every h1 read is warp-uniform (broadcast = 1 wavefront per
// LDS.128). W2/W1/W3/b2 live in registers. Cross-warp reduce via smem
// partials + a tiny combine stage.
//  * 1024 CTAs x 256 threads, 1 row/CTA, 2 CTAs/SM, LPT (longest-first)
//  * per-row exact step skipping; counting-sorted rows
//  * 4 light barriers/eval; fma.rn.f32x2; MUFU tanh.approx
// ---------------------------------------------------------------------------

#define Bsz   1024
#define Tn    128
#define Dn    256
#define NACT  9
#define LATD  32
#define INW   43
#define NCTA  1024
#define NTH   256

typedef unsigned long long u64;

__device__ int g_perm[Bsz];

__device__ __forceinline__ u64 fma2(u64 a, u64 b, u64 c) {
    u64 d;
    asm("fma.rn.f32x2 %0, %1, %2, %3;" : "=l"(d) : "l"(a), "l"(b), "l"(c));
    return d;
}
__device__ __forceinline__ u64 add2(u64 a, u64 b) {
    u64 d;
    asm("add.rn.f32x2 %0, %1, %2;" : "=l"(d) : "l"(a), "l"(b));
    return d;
}
__device__ __forceinline__ float2 unpk(u64 v) {
    float2 f;
    asm("mov.b64 {%0, %1}, %2;" : "=f"(f.x), "=f"(f.y) : "l"(v));
    return f;
}
__device__ __forceinline__ float tanh_fast(float x) {
    float r;
    asm("tanh.approx.f32 %0, %1;" : "=f"(r) : "f"(x));
    return r;
}

// ---- counting sort of rows by length (stable, deterministic) --------------
__global__ void sort_kernel(const int* __restrict__ length)
{
    __shared__ int len_s[Bsz];
    __shared__ int hist[Tn];
    __shared__ int pref[Tn];
    const int tid = threadIdx.x;          // 128 threads
    for (int i = tid; i < Bsz; i += 128) {
        int v = length[i];
        len_s[i] = min(max(v, 0), Tn - 1);
    }
    if (tid < Tn) hist[tid] = 0;
    __syncthreads();
    for (int i = tid; i < Bsz; i += 128) atomicAdd(&hist[len_s[i]], 1);
    __syncthreads();
    if (tid == 0) {
        int acc = 0;
        for (int v = 0; v < Tn; v++) { pref[v] = acc; acc += hist[v]; }
    }
    __syncthreads();
    int pos = pref[tid];                  // thread tid handles bin value tid
    for (int b = 0; b < Bsz; b++)
        if (len_s[b] == tid) g_perm[pos++] = b;
}

struct __align__(16) Smem {
    float h1[128];
    float h2[128];
    float part[2][128];     // layer-2 partial dots per k-half
    float csr[Dn];
    float Yts[12];
    float Ycur[12];
    float ksum[12];
    float b3s[16];
    float tsm[Tn];
    float tend;
    int   brow;
};

__global__ __launch_bounds__(NTH, 2)
void node_kernel(const float* __restrict__ ts, const float* __restrict__ y0,
                 const float* __restrict__ latent, const int* __restrict__ length,
                 const float* __restrict__ dense_ts, const float* __restrict__ dense_cs,
                 const float* __restrict__ W1, const float* __restrict__ b1,
                 const float* __restrict__ W2, const float* __restrict__ b2,
                 const float* __restrict__ W3, const float* __restrict__ b3,
                 float* __restrict__ out)
{
    __shared__ Smem s;
    const int tid = threadIdx.x;
    // longest-first launch: bid 0 = longest row -> LPT under work-stealing
    const int grp = (NCTA - 1) - blockIdx.x;

    if (tid == 0) {
        int b = g_perm[grp];
        s.brow = b;
        s.tend = ts[max(length[b] - 1, 0)];
    }
    if (tid < Tn) s.tsm[tid] = ts[tid];
    if (tid < NACT) s.b3s[tid] = b3[tid];
    if (tid < 12) { s.Yts[tid] = 0.f; s.Ycur[tid] = 0.f; s.ksum[tid] = 0.f; }
    __syncthreads();
    const int row = s.brow;

    // ---- per-thread register state ---------------------------------------
    // layer-2: warp-uniform k-half -> broadcast h1 reads
    const int w  = tid >> 5;
    const int l  = tid & 31;
    const int h  = w >> 2;               // warps 0-3: k in [0,64); warps 4-7: [64,128)
    const int u2 = (w & 3) * 32 + l;     // unit 0..127
    u64 W2r[32];
    {
        const u64* wg = reinterpret_cast<const u64*>(W2 + u2 * 128 + h * 64);
        #pragma unroll
        for (int m = 0; m < 32; m++) W2r[m] = wg[m];
    }

    // combine stage (threads 0..127): b2 in reg
    const float b2r = (tid < 128) ? b2[tid] : 0.f;

    // layer-1 (threads 128..255 <-> unit tid&127): W1 coefficients + folded bias
    float w1a[NACT], w1t = 0.f, w1c = 0.f, base1 = 0.f;
    if (tid >= 128) {
        const int u1 = tid & 127;
        const float* W1r = W1 + u1 * INW;
        #pragma unroll
        for (int i = 0; i < NACT; i++) w1a[i] = W1r[i];
        w1t = W1r[41];
        w1c = W1r[42];
        const float* lv = latent + row * LATD;
        float acc = b1[u1];
        #pragma unroll
        for (int li = 0; li < LATD; li++) acc = fmaf(W1r[9 + li], lv[li], acc);
        base1 = acc;
    }

    // layer-3 (threads 0..71): W3 slice in regs (i3 = tid>>3, q = tid&7)
    float4 w3r[4];
    if (tid < 72) {
        const float* wg = W3 + (tid >> 3) * 128 + (tid & 7) * 16;
        #pragma unroll
        for (int kk = 0; kk < 4; kk++)
            w3r[kk] = *reinterpret_cast<const float4*>(wg + kk * 4);
    }

    for (int d = tid; d < Dn; d += NTH)
        s.csr[d] = dense_cs[row * Dn + d];
    __syncthreads();
    if (tid == 0) {
        float y = y0[row];
        s.Yts[0] = y; s.Ycur[0] = y;
        out[row * Tn] = y;               // t = 0 sample
    }
    __syncthreads();

    // ---- time integration -------------------------------------------------
    for (int step = 0; step < Tn - 1; step++) {
        const float ta  = s.tsm[step];
        const float dtf = (s.tsm[step + 1] - ta) * 0.5f;
        if (ta <= s.tend) {
            for (int sub = 0; sub < 2; sub++) {
                const float t0 = ta + sub * dtf;
                for (int st = 0; st < 4; st++) {
                    const float t = t0 + ((st == 0) ? 0.f : (st == 3) ? dtf : 0.5f * dtf);

                    // ---- layer 1 (warps 4-7, one unit each; broadcast reads)
                    if (tid >= 128) {
                        int ii = (int)ceilf(t);
                        ii = max(1, min(Dn - 1, ii));
                        float wc = t - (float)(ii - 1);
                        wc = fminf(fmaxf(wc, 0.f), 1.f);
                        float cl = s.csr[ii - 1];
                        float c  = fmaf(wc, s.csr[ii] - cl, cl);
                        float4 yA = *reinterpret_cast<const float4*>(&s.Yts[0]);
                        float4 yB = *reinterpret_cast<const float4*>(&s.Yts[4]);
                        float  y8 = s.Yts[8];
                        float a0 = base1;
                        float a1 = w1t * t;
                        a0 = fmaf(w1c,   c,    a0);
                        a1 = fmaf(w1a[0], yA.x, a1);
                        a0 = fmaf(w1a[1], yA.y, a0);
                        a1 = fmaf(w1a[2], yA.z, a1);
                        a0 = fmaf(w1a[3], yA.w, a0);
                        a1 = fmaf(w1a[4], yB.x, a1);
                        a0 = fmaf(w1a[5], yB.y, a0);
                        a1 = fmaf(w1a[6], yB.z, a1);
                        a0 = fmaf(w1a[7], yB.w, a0);
                        a1 = fmaf(w1a[8], y8,   a1);
                        s.h1[tid & 127] = tanh_fast(a0 + a1);
                    }
                    __syncthreads();

                    // ---- layer 2 partial: broadcast h1, register W2 ----
                    {
                        u64 a0 = 0ull, a1 = 0ull, a2 = 0ull, a3 = 0ull;
                        const ulonglong2* hb =
                            reinterpret_cast<const ulonglong2*>(s.h1 + h * 64);
                        #pragma unroll
                        for (int m = 0; m < 8; m++) {
                            ulonglong2 v0 = hb[2 * m];       // broadcast: warp-uniform addr
                            a0 = fma2(W2r[4 * m],     v0.x, a0);
                            a1 = fma2(W2r[4 * m + 1], v0.y, a1);
                            ulonglong2 v1 = hb[2 * m + 1];
                            a2 = fma2(W2r[4 * m + 2], v1.x, a2);
                            a3 = fma2(W2r[4 * m + 3], v1.y, a3);
                        }
                        float2 f = unpk(add2(add2(a0, a1), add2(a2, a3)));
                        s.part[h][u2] = f.x + f.y;
                    }
                    __syncthreads();

                    // ---- layer 2 combine (warps 0-3): h2 = tanh(p0+p1+b2) ----
                    if (tid < 128)
                        s.h2[tid] = tanh_fast(s.part[0][tid] + s.part[1][tid] + b2r);
                    __syncthreads();

                    // ---- layer 3 + constraint + gating + RK bookkeeping ----
                    // 72 threads = warps 0,1 full + lanes 0..7 of warp 2
                    if (tid < 72) {
                        const unsigned mask = (tid < 64) ? 0xffffffffu : 0x000000ffu;
                        const int q  = tid & 7;      // 16-k slice
                        const int i3 = tid >> 3;     // output unit 0..8
                        const float4* hv = reinterpret_cast<const float4*>(&s.h2[q * 16]);
                        float ax = 0.f, ay = 0.f, az = 0.f, aw = 0.f;
                        #pragma unroll
                        for (int kk = 0; kk < 4; kk++) {
                            float4 a = w3r[kk], b = hv[kk];
                            ax = fmaf(a.x, b.x, ax);
                            ay = fmaf(a.y, b.y, ay);
                            az = fmaf(a.z, b.z, az);
                            aw = fmaf(a.w, b.w, aw);
                        }
                        float acc = (ax + ay) + (az + aw);
                        acc += __shfl_xor_sync(mask, acc, 1);
                        acc += __shfl_xor_sync(mask, acc, 2);
                        acc += __shfl_xor_sync(mask, acc, 4);
                        if (q == 0) {
                            acc += s.b3s[i3];
                            if (i3 == 0) acc = -__cosf(acc);
                            if (t > s.tend) acc = 0.f;       // per-sample stop
                            float ks;
                            if (st == 0) { ks = acc; s.ksum[i3] = ks; }
                            else {
                                ks = s.ksum[i3];
                                if (st < 3) { ks += 2.f * acc; s.ksum[i3] = ks; }
                            }
                            if (st < 3) {
                                float cY = (st == 2) ? dtf : 0.5f * dtf;
                                s.Yts[i3] = s.Ycur[i3] + cY * acc;
                            } else {
                                float y = s.Ycur[i3]
                                        + (dtf * (1.0f / 6.0f)) * (ks + acc);
                                s.Ycur[i3] = y;
                                s.Yts[i3]  = y;
                            }
                        }
                    }
                    __syncthreads();
                }
            }
        }
        if (tid == 0)
            out[row * Tn + step + 1] = s.Ycur[0];
    }
}

extern "C" void kernel_launch(void* const* d_in, const int* in_sizes, int n_in,
                              void* d_out, int out_size)
{
    (void)in_sizes; (void)n_in; (void)out_size;
    sort_kernel<<<1, 128>>>((const int*)d_in[3]);
    node_kernel<<<NCTA, NTH>>>(
        (const float*)d_in[0],   // ts
        (const float*)d_in[1],   // y0
        (const float*)d_in[2],   // latent_vec
        (const int*)  d_in[3],   // length
        (const float*)d_in[4],   // dense_ts (arange -> index math)
        (const float*)d_in[5],   // dense_cs
        (const float*)d_in[6],   // W1
        (const float*)d_in[7],   // b1
        (const float*)d_in[8],   // W2
        (const float*)d_in[9],   // b2
        (const float*)d_in[10],  // W3
        (const float*)d_in[11],  // b3
        (float*)d_out);
}

// round 10
// speedup vs baseline: 1.4029x; 1.2196x over previous
#include <cuda_runtime.h>
#include <math.h>

// ---------------------------------------------------------------------------
// NeuralODE on GB300 (round 10): broadcast layer-2 (r9, validated: L1 83->59)
// + 2 length-adjacent rows per CTA to amortize barriers and parallelize the
// serial tail stages across rows. 512 CTAs x 256 threads, 2 CTAs/SM -> 4
// independent rows in flight per SM (work-throughput regime, issue-eff bound).
//  * rows counting-sorted by length; pair skip = max(pair tend), ~exact
//  * longest-first launch (LPT under HW work-stealing)
//  * W2/W1/W3/b2 in registers; all smem reads warp-uniform (broadcast)
//  * fma.rn.f32x2 / add.rn.f32x2, MUFU tanh.approx
// ---------------------------------------------------------------------------

#define Bsz   1024
#define Tn    128
#define Dn    256
#define NACT  9
#define LATD  32
#define INW   43
#define RR    2
#define NCTA  512
#define NTH   256

typedef unsigned long long u64;

__device__ int g_perm[Bsz];

__device__ __forceinline__ u64 fma2(u64 a, u64 b, u64 c) {
    u64 d;
    asm("fma.rn.f32x2 %0, %1, %2, %3;" : "=l"(d) : "l"(a), "l"(b), "l"(c));
    return d;
}
__device__ __forceinline__ u64 add2(u64 a, u64 b) {
    u64 d;
    asm("add.rn.f32x2 %0, %1, %2;" : "=l"(d) : "l"(a), "l"(b));
    return d;
}
__device__ __forceinline__ float2 unpk(u64 v) {
    float2 f;
    asm("mov.b64 {%0, %1}, %2;" : "=f"(f.x), "=f"(f.y) : "l"(v));
    return f;
}
__device__ __forceinline__ float tanh_fast(float x) {
    float r;
    asm("tanh.approx.f32 %0, %1;" : "=f"(r) : "f"(x));
    return r;
}

// ---- counting sort of rows by length (stable, deterministic) --------------
__global__ void sort_kernel(const int* __restrict__ length)
{
    __shared__ int len_s[Bsz];
    __shared__ int hist[Tn];
    __shared__ int pref[Tn];
    const int tid = threadIdx.x;          // 128 threads
    for (int i = tid; i < Bsz; i += 128) {
        int v = length[i];
        len_s[i] = min(max(v, 0), Tn - 1);
    }
    if (tid < Tn) hist[tid] = 0;
    __syncthreads();
    for (int i = tid; i < Bsz; i += 128) atomicAdd(&hist[len_s[i]], 1);
    __syncthreads();
    if (tid == 0) {
        int acc = 0;
        for (int v = 0; v < Tn; v++) { pref[v] = acc; acc += hist[v]; }
    }
    __syncthreads();
    int pos = pref[tid];                  // thread tid handles bin value tid
    for (int b = 0; b < Bsz; b++)
        if (len_s[b] == tid) g_perm[pos++] = b;
}

struct __align__(16) Smem {
    float h1[RR][128];
    float h2[RR][128];
    float part[2][RR][128];   // [k-half][row][unit]
    float csr[RR][Dn];
    float Yts[RR][12];
    float Ycur[RR][12];
    float ksum[RR][12];
    float b3s[16];
    float tsm[Tn];
    float tend[RR];
    float tendmax;
    int   brow[RR];
};

__global__ __launch_bounds__(NTH, 2)
void node_kernel(const float* __restrict__ ts, const float* __restrict__ y0,
                 const float* __restrict__ latent, const int* __restrict__ length,
                 const float* __restrict__ dense_ts, const float* __restrict__ dense_cs,
                 const float* __restrict__ W1, const float* __restrict__ b1,
                 const float* __restrict__ W2, const float* __restrict__ b2,
                 const float* __restrict__ W3, const float* __restrict__ b3,
                 float* __restrict__ out)
{
    __shared__ Smem s;
    const int tid = threadIdx.x;
    // longest-first launch: bid 0 = longest pair -> LPT under work-stealing
    const int grp = (NCTA - 1) - blockIdx.x;

    if (tid < RR) {
        int b = g_perm[grp * RR + tid];
        s.brow[tid] = b;
        s.tend[tid] = ts[max(length[b] - 1, 0)];
    }
    if (tid < Tn) s.tsm[tid] = ts[tid];
    if (tid < NACT) s.b3s[tid] = b3[tid];
    if (tid < RR * 12) {
        int r = tid / 12, d = tid % 12;
        s.Yts[r][d] = 0.f; s.Ycur[r][d] = 0.f; s.ksum[r][d] = 0.f;
    }
    __syncthreads();
    if (tid == 0) s.tendmax = fmaxf(s.tend[0], s.tend[1]);

    // ---- per-thread register state ---------------------------------------
    // layer-1 & combine: thread = (unit u1, row e)
    const int u1 = tid & 127;
    const int e  = tid >> 7;
    // layer-2: warp-uniform k-half -> broadcast h1 reads
    const int w  = tid >> 5;
    const int l  = tid & 31;
    const int h  = w >> 2;               // warps 0-3: k in [0,64); warps 4-7: [64,128)
    const int u2 = (w & 3) * 32 + l;     // unit 0..127

    u64 W2r[32];
    {
        const u64* wg = reinterpret_cast<const u64*>(W2 + u2 * 128 + h * 64);
        #pragma unroll
        for (int m = 0; m < 32; m++) W2r[m] = wg[m];
    }
    const float b2r = b2[u1];

    // layer-1: W1 coefficients + folded latent bias for (u1, e)
    float w1a[NACT], w1t, w1c, base1;
    {
        const float* W1r = W1 + u1 * INW;
        #pragma unroll
        for (int i = 0; i < NACT; i++) w1a[i] = W1r[i];
        w1t = W1r[41];
        w1c = W1r[42];
        const float* lv = latent + g_perm[grp * RR + e] * LATD;
        float acc = b1[u1];
        #pragma unroll
        for (int li = 0; li < LATD; li++) acc = fmaf(W1r[9 + li], lv[li], acc);
        base1 = acc;
    }

    // layer-3 (threads 0..143): W3 slice in regs; (q = tid&7, r = (tid>>3)&1, i3 = tid>>4)
    float4 w3r[4];
    if (tid < 144) {
        const float* wg = W3 + (tid >> 4) * 128 + (tid & 7) * 16;
        #pragma unroll
        for (int kk = 0; kk < 4; kk++)
            w3r[kk] = *reinterpret_cast<const float4*>(wg + kk * 4);
    }

    for (int idx = tid; idx < RR * Dn; idx += NTH) {
        int r = idx >> 8, d = idx & 255;
        s.csr[r][d] = dense_cs[s.brow[r] * Dn + d];
    }
    __syncthreads();
    if (tid < RR) {
        float y = y0[s.brow[tid]];
        s.Yts[tid][0] = y; s.Ycur[tid][0] = y;
        out[s.brow[tid] * Tn] = y;       // t = 0 sample
    }
    __syncthreads();

    // ---- time integration -------------------------------------------------
    for (int step = 0; step < Tn - 1; step++) {
        const float ta  = s.tsm[step];
        const float dtf = (s.tsm[step + 1] - ta) * 0.5f;
        if (ta <= s.tendmax) {
            for (int sub = 0; sub < 2; sub++) {
                const float t0 = ta + sub * dtf;
                for (int st = 0; st < 4; st++) {
                    const float t = t0 + ((st == 0) ? 0.f : (st == 3) ? dtf : 0.5f * dtf);

                    // ---- layer 1: all 256 threads, one (unit,row) each ----
                    {
                        int ii = (int)ceilf(t);
                        ii = max(1, min(Dn - 1, ii));
                        float wc = t - (float)(ii - 1);
                        wc = fminf(fmaxf(wc, 0.f), 1.f);
                        float cl = s.csr[e][ii - 1];
                        float c  = fmaf(wc, s.csr[e][ii] - cl, cl);
                        float4 yA = *reinterpret_cast<const float4*>(&s.Yts[e][0]);
                        float4 yB = *reinterpret_cast<const float4*>(&s.Yts[e][4]);
                        float  y8 = s.Yts[e][8];
                        float a0 = base1;
                        float a1 = w1t * t;
                        a0 = fmaf(w1c,   c,    a0);
                        a1 = fmaf(w1a[0], yA.x, a1);
                        a0 = fmaf(w1a[1], yA.y, a0);
                        a1 = fmaf(w1a[2], yA.z, a1);
                        a0 = fmaf(w1a[3], yA.w, a0);
                        a1 = fmaf(w1a[4], yB.x, a1);
                        a0 = fmaf(w1a[5], yB.y, a0);
                        a1 = fmaf(w1a[6], yB.z, a1);
                        a0 = fmaf(w1a[7], yB.w, a0);
                        a1 = fmaf(w1a[8], y8,   a1);
                        s.h1[e][u1] = tanh_fast(a0 + a1);
                    }
                    __syncthreads();

                    // ---- layer 2 partials: broadcast h1, register W2, 2 rows
                    {
                        #pragma unroll
                        for (int r = 0; r < RR; r++) {
                            u64 a0 = 0ull, a1 = 0ull, a2 = 0ull, a3 = 0ull;
                            const ulonglong2* hb =
                                reinterpret_cast<const ulonglong2*>(&s.h1[r][h * 64]);
                            #pragma unroll
                            for (int m = 0; m < 8; m++) {
                                ulonglong2 v0 = hb[2 * m];   // warp-uniform addr: broadcast
                                a0 = fma2(W2r[4 * m],     v0.x, a0);
                                a1 = fma2(W2r[4 * m + 1], v0.y, a1);
                                ulonglong2 v1 = hb[2 * m + 1];
                                a2 = fma2(W2r[4 * m + 2], v1.x, a2);
                                a3 = fma2(W2r[4 * m + 3], v1.y, a3);
                            }
                            float2 f = unpk(add2(add2(a0, a1), add2(a2, a3)));
                            s.part[h][r][u2] = f.x + f.y;
                        }
                    }
                    __syncthreads();

                    // ---- layer 2 combine: all 256 threads (unit,row) ----
                    s.h2[e][u1] = tanh_fast(s.part[0][e][u1] + s.part[1][e][u1] + b2r);
                    __syncthreads();

                    // ---- layer 3 + constraint + gating + RK bookkeeping ----
                    // 144 threads = warps 0-3 full + lanes 0..15 of warp 4
                    if (tid < 144) {
                        const unsigned mask = (tid < 128) ? 0xffffffffu : 0x0000ffffu;
                        const int q  = tid & 7;          // 16-k slice
                        const int r  = (tid >> 3) & 1;   // row
                        const int i3 = tid >> 4;         // output unit 0..8
                        const float4* hv = reinterpret_cast<const float4*>(&s.h2[r][q * 16]);
                        float ax = 0.f, ay = 0.f, az = 0.f, aw = 0.f;
                        #pragma unroll
                        for (int kk = 0; kk < 4; kk++) {
                            float4 a = w3r[kk], b = hv[kk];
                            ax = fmaf(a.x, b.x, ax);
                            ay = fmaf(a.y, b.y, ay);
                            az = fmaf(a.z, b.z, az);
                            aw = fmaf(a.w, b.w, aw);
                        }
                        float acc = (ax + ay) + (az + aw);
                        acc += __shfl_xor_sync(mask, acc, 1);
                        acc += __shfl_xor_sync(mask, acc, 2);
                        acc += __shfl_xor_sync(mask, acc, 4);
                        if (q == 0) {
                            acc += s.b3s[i3];
                            if (i3 == 0) acc = -__cosf(acc);
                            if (t > s.tend[r]) acc = 0.f;     // per-sample stop
                            float ks;
                            if (st == 0) { ks = acc; s.ksum[r][i3] = ks; }
                            else {
                                ks = s.ksum[r][i3];
                                if (st < 3) { ks += 2.f * acc; s.ksum[r][i3] = ks; }
                            }
                            if (st < 3) {
                                float cY = (st == 2) ? dtf : 0.5f * dtf;
                                s.Yts[r][i3] = s.Ycur[r][i3] + cY * acc;
                            } else {
                                float y = s.Ycur[r][i3]
                                        + (dtf * (1.0f / 6.0f)) * (ks + acc);
                                s.Ycur[r][i3] = y;
                                s.Yts[r][i3]  = y;
                            }
                        }
                    }
                    __syncthreads();
                }
            }
        }
        if (tid < RR)
            out[s.brow[tid] * Tn + step + 1] = s.Ycur[tid][0];
    }
}

extern "C" void kernel_launch(void* const* d_in, const int* in_sizes, int n_in,
                              void* d_out, int out_size)
{
    (void)in_sizes; (void)n_in; (void)out_size;
    sort_kernel<<<1, 128>>>((const int*)d_in[3]);
    node_kernel<<<NCTA, NTH>>>(
        (const float*)d_in[0],   // ts
        (const float*)d_in[1],   // y0
        (const float*)d_in[2],   // latent_vec
        (const int*)  d_in[3],   // length
        (const float*)d_in[4],   // dense_ts (arange -> index math)
        (const float*)d_in[5],   // dense_cs
        (const float*)d_in[6],   // W1
        (const float*)d_in[7],   // b1
        (const float*)d_in[8],   // W2
        (const float*)d_in[9],   // b2
        (const float*)d_in[10],  // W3
        (const float*)d_in[11],  // b3
        (float*)d_out);
}

// round 11
// speedup vs baseline: 1.4863x; 1.0595x over previous
#include <cuda_runtime.h>
#include <math.h>

// ---------------------------------------------------------------------------
// NeuralODE on GB300 (round 10): broadcast layer-2 (r9, validated: L1 83->59)
// + 2 length-adjacent rows per CTA to amortize barriers and parallelize the
// serial tail stages across rows. 512 CTAs x 256 threads, 2 CTAs/SM -> 4
// independent rows in flight per SM (work-throughput regime, issue-eff bound).
//  * rows counting-sorted by length; pair skip = max(pair tend), ~exact
//  * longest-first launch (LPT under HW work-stealing)
//  * W2/W1/W3/b2 in registers; all smem reads warp-uniform (broadcast)
//  * fma.rn.f32x2 / add.rn.f32x2, MUFU tanh.approx
// ---------------------------------------------------------------------------

#define Bsz   1024
#define Tn    128
#define Dn    256
#define NACT  9
#define LATD  32
#define INW   43
#define RR    2
#define NCTA  512
#define NTH   256

typedef unsigned long long u64;

__device__ int g_perm[Bsz];

__device__ __forceinline__ u64 fma2(u64 a, u64 b, u64 c) {
    u64 d;
    asm("fma.rn.f32x2 %0, %1, %2, %3;" : "=l"(d) : "l"(a), "l"(b), "l"(c));
    return d;
}
__device__ __forceinline__ u64 add2(u64 a, u64 b) {
    u64 d;
    asm("add.rn.f32x2 %0, %1, %2;" : "=l"(d) : "l"(a), "l"(b));
    return d;
}
__device__ __forceinline__ float2 unpk(u64 v) {
    float2 f;
    asm("mov.b64 {%0, %1}, %2;" : "=f"(f.x), "=f"(f.y) : "l"(v));
    return f;
}
__device__ __forceinline__ float tanh_fast(float x) {
    float r;
    asm("tanh.approx.f32 %0, %1;" : "=f"(r) : "f"(x));
    return r;
}

// ---- counting sort of rows by length (stable, deterministic) --------------
__global__ void sort_kernel(const int* __restrict__ length)
{
    __shared__ int len_s[Bsz];
    __shared__ int hist[Tn];
    __shared__ int pref[Tn];
    const int tid = threadIdx.x;          // 128 threads
    for (int i = tid; i < Bsz; i += 128) {
        int v = length[i];
        len_s[i] = min(max(v, 0), Tn - 1);
    }
    if (tid < Tn) hist[tid] = 0;
    __syncthreads();
    for (int i = tid; i < Bsz; i += 128) atomicAdd(&hist[len_s[i]], 1);
    __syncthreads();
    if (tid == 0) {
        int acc = 0;
        for (int v = 0; v < Tn; v++) { pref[v] = acc; acc += hist[v]; }
    }
    __syncthreads();
    int pos = pref[tid];                  // thread tid handles bin value tid
    for (int b = 0; b < Bsz; b++)
        if (len_s[b] == tid) g_perm[pos++] = b;
}

struct __align__(16) Smem {
    float h1[RR][128];
    float h2[RR][128];
    float part[2][RR][128];   // [k-half][row][unit]
    float csr[RR][Dn];
    float Yts[RR][12];
    float Ycur[RR][12];
    float ksum[RR][12];
    float b3s[16];
    float tsm[Tn];
    float tend[RR];
    float tendmax;
    int   brow[RR];
};

__global__ __launch_bounds__(NTH, 2)
void node_kernel(const float* __restrict__ ts, const float* __restrict__ y0,
                 const float* __restrict__ latent, const int* __restrict__ length,
                 const float* __restrict__ dense_ts, const float* __restrict__ dense_cs,
                 const float* __restrict__ W1, const float* __restrict__ b1,
                 const float* __restrict__ W2, const float* __restrict__ b2,
                 const float* __restrict__ W3, const float* __restrict__ b3,
                 float* __restrict__ out)
{
    __shared__ Smem s;
    const int tid = threadIdx.x;
    // longest-first launch: bid 0 = longest pair -> LPT under work-stealing
    const int grp = (NCTA - 1) - blockIdx.x;

    if (tid < RR) {
        int b = g_perm[grp * RR + tid];
        s.brow[tid] = b;
        s.tend[tid] = ts[max(length[b] - 1, 0)];
    }
    if (tid < Tn) s.tsm[tid] = ts[tid];
    if (tid < NACT) s.b3s[tid] = b3[tid];
    if (tid < RR * 12) {
        int r = tid / 12, d = tid % 12;
        s.Yts[r][d] = 0.f; s.Ycur[r][d] = 0.f; s.ksum[r][d] = 0.f;
    }
    __syncthreads();
    if (tid == 0) s.tendmax = fmaxf(s.tend[0], s.tend[1]);

    // ---- per-thread register state ---------------------------------------
    // layer-1 & combine: thread = (unit u1, row e)
    const int u1 = tid & 127;
    const int e  = tid >> 7;
    // layer-2: warp-uniform k-half -> broadcast h1 reads
    const int w  = tid >> 5;
    const int l  = tid & 31;
    const int h  = w >> 2;               // warps 0-3: k in [0,64); warps 4-7: [64,128)
    const int u2 = (w & 3) * 32 + l;     // unit 0..127

    u64 W2r[32];
    {
        const u64* wg = reinterpret_cast<const u64*>(W2 + u2 * 128 + h * 64);
        #pragma unroll
        for (int m = 0; m < 32; m++) W2r[m] = wg[m];
    }
    const float b2r = b2[u1];

    // layer-1: W1 coefficients + folded latent bias for (u1, e)
    float w1a[NACT], w1t, w1c, base1;
    {
        const float* W1r = W1 + u1 * INW;
        #pragma unroll
        for (int i = 0; i < NACT; i++) w1a[i] = W1r[i];
        w1t = W1r[41];
        w1c = W1r[42];
        const float* lv = latent + g_perm[grp * RR + e] * LATD;
        float acc = b1[u1];
        #pragma unroll
        for (int li = 0; li < LATD; li++) acc = fmaf(W1r[9 + li], lv[li], acc);
        base1 = acc;
    }

    // layer-3 (threads 0..143): W3 slice in regs; (q = tid&7, r = (tid>>3)&1, i3 = tid>>4)
    float4 w3r[4];
    if (tid < 144) {
        const float* wg = W3 + (tid >> 4) * 128 + (tid & 7) * 16;
        #pragma unroll
        for (int kk = 0; kk < 4; kk++)
            w3r[kk] = *reinterpret_cast<const float4*>(wg + kk * 4);
    }

    for (int idx = tid; idx < RR * Dn; idx += NTH) {
        int r = idx >> 8, d = idx & 255;
        s.csr[r][d] = dense_cs[s.brow[r] * Dn + d];
    }
    __syncthreads();
    if (tid < RR) {
        float y = y0[s.brow[tid]];
        s.Yts[tid][0] = y; s.Ycur[tid][0] = y;
        out[s.brow[tid] * Tn] = y;       // t = 0 sample
    }
    __syncthreads();

    // ---- time integration -------------------------------------------------
    for (int step = 0; step < Tn - 1; step++) {
        const float ta  = s.tsm[step];
        const float dtf = (s.tsm[step + 1] - ta) * 0.5f;
        if (ta <= s.tendmax) {
            for (int sub = 0; sub < 2; sub++) {
                const float t0 = ta + sub * dtf;
                for (int st = 0; st < 4; st++) {
                    const float t = t0 + ((st == 0) ? 0.f : (st == 3) ? dtf : 0.5f * dtf);

                    // ---- layer 1: all 256 threads, one (unit,row) each ----
                    {
                        int ii = (int)ceilf(t);
                        ii = max(1, min(Dn - 1, ii));
                        float wc = t - (float)(ii - 1);
                        wc = fminf(fmaxf(wc, 0.f), 1.f);
                        float cl = s.csr[e][ii - 1];
                        float c  = fmaf(wc, s.csr[e][ii] - cl, cl);
                        float4 yA = *reinterpret_cast<const float4*>(&s.Yts[e][0]);
                        float4 yB = *reinterpret_cast<const float4*>(&s.Yts[e][4]);
                        float  y8 = s.Yts[e][8];
                        float a0 = base1;
                        float a1 = w1t * t;
                        a0 = fmaf(w1c,   c,    a0);
                        a1 = fmaf(w1a[0], yA.x, a1);
                        a0 = fmaf(w1a[1], yA.y, a0);
                        a1 = fmaf(w1a[2], yA.z, a1);
                        a0 = fmaf(w1a[3], yA.w, a0);
                        a1 = fmaf(w1a[4], yB.x, a1);
                        a0 = fmaf(w1a[5], yB.y, a0);
                        a1 = fmaf(w1a[6], yB.z, a1);
                        a0 = fmaf(w1a[7], yB.w, a0);
                        a1 = fmaf(w1a[8], y8,   a1);
                        s.h1[e][u1] = tanh_fast(a0 + a1);
                    }
                    __syncthreads();

                    // ---- layer 2 partials: broadcast h1, register W2, 2 rows
                    {
                        #pragma unroll
                        for (int r = 0; r < RR; r++) {
                            u64 a0 = 0ull, a1 = 0ull, a2 = 0ull, a3 = 0ull;
                            const ulonglong2* hb =
                                reinterpret_cast<const ulonglong2*>(&s.h1[r][h * 64]);
                            #pragma unroll
                            for (int m = 0; m < 8; m++) {
                                ulonglong2 v0 = hb[2 * m];   // warp-uniform addr: broadcast
                                a0 = fma2(W2r[4 * m],     v0.x, a0);
                                a1 = fma2(W2r[4 * m + 1], v0.y, a1);
                                ulonglong2 v1 = hb[2 * m + 1];
                                a2 = fma2(W2r[4 * m + 2], v1.x, a2);
                                a3 = fma2(W2r[4 * m + 3], v1.y, a3);
                            }
                            float2 f = unpk(add2(add2(a0, a1), add2(a2, a3)));
                            s.part[h][r][u2] = f.x + f.y;
                        }
                    }
                    __syncthreads();

                    // ---- layer 2 combine: all 256 threads (unit,row) ----
                    s.h2[e][u1] = tanh_fast(s.part[0][e][u1] + s.part[1][e][u1] + b2r);
                    __syncthreads();

                    // ---- layer 3 + constraint + gating + RK bookkeeping ----
                    // 144 threads = warps 0-3 full + lanes 0..15 of warp 4
                    if (tid < 144) {
                        const unsigned mask = (tid < 128) ? 0xffffffffu : 0x0000ffffu;
                        const int q  = tid & 7;          // 16-k slice
                        const int r  = (tid >> 3) & 1;   // row
                        const int i3 = tid >> 4;         // output unit 0..8
                        const float4* hv = reinterpret_cast<const float4*>(&s.h2[r][q * 16]);
                        float ax = 0.f, ay = 0.f, az = 0.f, aw = 0.f;
                        #pragma unroll
                        for (int kk = 0; kk < 4; kk++) {
                            float4 a = w3r[kk], b = hv[kk];
                            ax = fmaf(a.x, b.x, ax);
                            ay = fmaf(a.y, b.y, ay);
                            az = fmaf(a.z, b.z, az);
                            aw = fmaf(a.w, b.w, aw);
                        }
                        float acc = (ax + ay) + (az + aw);
                        acc += __shfl_xor_sync(mask, acc, 1);
                        acc += __shfl_xor_sync(mask, acc, 2);
                        acc += __shfl_xor_sync(mask, acc, 4);
                        if (q == 0) {
                            acc += s.b3s[i3];
                            if (i3 == 0) acc = -__cosf(acc);
                            if (t > s.tend[r]) acc = 0.f;     // per-sample stop
                            float ks;
                            if (st == 0) { ks = acc; s.ksum[r][i3] = ks; }
                            else {
                                ks = s.ksum[r][i3];
                                if (st < 3) { ks += 2.f * acc; s.ksum[r][i3] = ks; }
                            }
                            if (st < 3) {
                                float cY = (st == 2) ? dtf : 0.5f * dtf;
                                s.Yts[r][i3] = s.Ycur[r][i3] + cY * acc;
                            } else {
                                float y = s.Ycur[r][i3]
                                        + (dtf * (1.0f / 6.0f)) * (ks + acc);
                                s.Ycur[r][i3] = y;
                                s.Yts[r][i3]  = y;
                            }
                        }
                    }
                    __syncthreads();
                }
            }
        }
        if (tid < RR)
            out[s.brow[tid] * Tn + step + 1] = s.Ycur[tid][0];
    }
}

extern "C" void kernel_launch(void* const* d_in, const int* in_sizes, int n_in,
                              void* d_out, int out_size)
{
    (void)in_sizes; (void)n_in; (void)out_size;
    sort_kernel<<<1, 128>>>((const int*)d_in[3]);
    node_kernel<<<NCTA, NTH>>>(
        (const float*)d_in[0],   // ts
        (const float*)d_in[1],   // y0
        (const float*)d_in[2],   // latent_vec
        (const int*)  d_in[3],   // length
        (const float*)d_in[4],   // dense_ts (arange -> index math)
        (const float*)d_in[5],   // dense_cs
        (const float*)d_in[6],   // W1
        (const float*)d_in[7],   // b1
        (const float*)d_in[8],   // W2
        (const float*)d_in[9],   // b2
        (const float*)d_in[10],  // W3
        (const float*)d_in[11],  // b3
        (float*)d_out);
}